// round 1
// baseline (speedup 1.0000x reference)
#include <cuda_runtime.h>
#include <cuda_bf16.h>
#include <math.h>

// ---------------------------------------------------------------------------
// GATLayers: 2x (GATConv -> BatchNorm -> ReLU) on a fixed graph.
//   N=20000 nodes, E=640000 edges (+N self loops), F=64, H=2 heads
//   layer1: C1=64  -> D1=128 out, layer2: C2=128 -> D2=256 out
// Strategy:
//   1. Build CSR-by-dst each call (histogram, block scan, scatter).
//   2. hx = X @ W (fp32 tiled GEMM), per-node attention scores a_s,a_d.
//   3. Per (node,head) warp: two-pass segment softmax + weighted gather-sum.
//      Self-loop handled analytically. Zero atomics on fat data.
//   4. BN: deterministic 2-stage column reduction, fused scale/shift+ReLU.
// ---------------------------------------------------------------------------

constexpr int NN = 20000;
constexpr int EE = 640000;
constexpr int FF = 64;
constexpr int D1 = 128;   // H*C1
constexpr int D2 = 256;   // H*C2

// ------------------------------ scratch ------------------------------------
__device__ int   g_is64;
__device__ int   g_deg[NN];
__device__ int   g_rowptr[NN + 1];
__device__ int   g_cursor[NN];
__device__ int   g_col[EE];
__device__ float g_hx1[NN * D1];
__device__ float g_as1[NN * 2];
__device__ float g_ad1[NN * 2];
__device__ float g_out1[NN * D1];
__device__ float g_hx2[NN * D2];
__device__ float g_as2[NN * 2];
__device__ float g_ad2[NN * 2];
__device__ float g_out2[NN * D2];
__device__ float g_part[100 * 2 * 256];
__device__ float g_scale[256];
__device__ float g_shift[256];

// -------------------------- CSR construction -------------------------------
__global__ void zero_detect_kernel(const int* __restrict__ ei32) {
    int i = blockIdx.x * blockDim.x + threadIdx.x;
    if (i < NN) g_deg[i] = 0;
    if (i == 0) {
        // int64 edge_index has zero high words (values < 2^31); int32 doesn't.
        int is64 = 1;
        for (int k = 0; k < 64; k++)
            if (ei32[2 * k + 1] != 0) { is64 = 0; break; }
        g_is64 = is64;
    }
}

__device__ __forceinline__ int edge_val(const void* ei, int idx, int is64) {
    if (is64) return (int)((const long long*)ei)[idx];
    return ((const int*)ei)[idx];
}

__global__ void hist_kernel(const void* __restrict__ ei) {
    int e = blockIdx.x * blockDim.x + threadIdx.x;
    if (e >= EE) return;
    int is64 = g_is64;
    int dst = edge_val(ei, EE + e, is64);
    atomicAdd(&g_deg[dst], 1);
}

__global__ __launch_bounds__(1024) void scan_kernel() {
    __shared__ int s[1024];
    const int t = threadIdx.x;
    const int chunk = (NN + 1023) / 1024;  // 20
    int lo = t * chunk;
    int hi = lo + chunk; if (hi > NN) hi = NN;
    if (lo > NN) lo = NN;
    int sum = 0;
    for (int i = lo; i < hi; i++) sum += g_deg[i];
    s[t] = sum;
    __syncthreads();
    // Hillis-Steele inclusive scan
    for (int off = 1; off < 1024; off <<= 1) {
        int v = (t >= off) ? s[t - off] : 0;
        __syncthreads();
        s[t] += v;
        __syncthreads();
    }
    int run = s[t] - sum;  // exclusive prefix
    for (int i = lo; i < hi; i++) {
        g_rowptr[i] = run;
        g_cursor[i] = run;
        run += g_deg[i];
    }
    if (t == 1023) g_rowptr[NN] = s[1023];
}

__global__ void scatter_kernel(const void* __restrict__ ei) {
    int e = blockIdx.x * blockDim.x + threadIdx.x;
    if (e >= EE) return;
    int is64 = g_is64;
    int src = edge_val(ei, e, is64);
    int dst = edge_val(ei, EE + e, is64);
    int pos = atomicAdd(&g_cursor[dst], 1);
    g_col[pos] = src;
}

// ------------------------------- GEMM --------------------------------------
// C[M,Ncol] = A[M,K] @ B[K,Ncol], fp32. BM=64, BN=128, BK=32, 256 threads,
// each thread computes 8x4 outputs.
__global__ __launch_bounds__(256) void gemm_kernel(
    const float* __restrict__ A, const float* __restrict__ B,
    float* __restrict__ C, int M, int K, int Ncol)
{
    __shared__ float As[64 * 32];
    __shared__ float Bs[32 * 128];
    const int tid = threadIdx.x;
    const int row0 = blockIdx.x * 64;
    const int col0 = blockIdx.y * 128;
    const int tx = tid & 31;
    const int ty = tid >> 5;
    float acc[8][4];
    #pragma unroll
    for (int i = 0; i < 8; i++)
        #pragma unroll
        for (int j = 0; j < 4; j++) acc[i][j] = 0.f;

    for (int k0 = 0; k0 < K; k0 += 32) {
        #pragma unroll
        for (int i = 0; i < 8; i++) {           // 64*32/256 = 8
            int idx = tid + i * 256;
            int r = idx >> 5, c = idx & 31;
            int gr = row0 + r;
            As[idx] = (gr < M) ? A[(size_t)gr * K + k0 + c] : 0.f;
        }
        #pragma unroll
        for (int i = 0; i < 16; i++) {          // 32*128/256 = 16
            int idx = tid + i * 256;
            int r = idx >> 7, c = idx & 127;
            Bs[idx] = B[(size_t)(k0 + r) * Ncol + col0 + c];
        }
        __syncthreads();
        #pragma unroll
        for (int kk = 0; kk < 32; kk++) {
            float a[8];
            #pragma unroll
            for (int i = 0; i < 8; i++) a[i] = As[(ty * 8 + i) * 32 + kk];
            float4 b = ((const float4*)Bs)[kk * 32 + tx];
            #pragma unroll
            for (int i = 0; i < 8; i++) {
                acc[i][0] += a[i] * b.x;
                acc[i][1] += a[i] * b.y;
                acc[i][2] += a[i] * b.z;
                acc[i][3] += a[i] * b.w;
            }
        }
        __syncthreads();
    }
    #pragma unroll
    for (int i = 0; i < 8; i++) {
        int gr = row0 + ty * 8 + i;
        if (gr < M) {
            float4 v = make_float4(acc[i][0], acc[i][1], acc[i][2], acc[i][3]);
            ((float4*)C)[((size_t)gr * Ncol + col0) / 4 + tx] = v;
        }
    }
}

// --------------------------- attention scores ------------------------------
// a_s[n,h] = hx[n,h,:] . att_src[h,:] ; a_d likewise. One warp per node.
__global__ __launch_bounds__(256) void scores_kernel(
    const float* __restrict__ hx, const float* __restrict__ att_s,
    const float* __restrict__ att_d, float* __restrict__ as_out,
    float* __restrict__ ad_out, int C)
{
    const int lane = threadIdx.x & 31;
    const int warp = threadIdx.x >> 5;
    const int node = blockIdx.x * 8 + warp;
    const int D = 2 * C;
    float s0 = 0.f, s1 = 0.f, d0 = 0.f, d1 = 0.f;
    const float* row = hx + (size_t)node * D;
    for (int c = lane; c < D; c += 32) {
        float v = row[c];
        float a = att_s[c];
        float b = att_d[c];
        if (c < C) { s0 += v * a; d0 += v * b; }
        else       { s1 += v * a; d1 += v * b; }
    }
    #pragma unroll
    for (int o = 16; o; o >>= 1) {
        s0 += __shfl_xor_sync(0xffffffffu, s0, o);
        s1 += __shfl_xor_sync(0xffffffffu, s1, o);
        d0 += __shfl_xor_sync(0xffffffffu, d0, o);
        d1 += __shfl_xor_sync(0xffffffffu, d1, o);
    }
    if (lane == 0) {
        as_out[node * 2 + 0] = s0;
        as_out[node * 2 + 1] = s1;
        ad_out[node * 2 + 0] = d0;
        ad_out[node * 2 + 1] = d1;
    }
}

// ------------------- segment softmax + weighted aggregate ------------------
// One warp per (node, head). Two passes: max, then exp/sum/weighted gather.
template <int C>
__global__ __launch_bounds__(256) void agg_kernel(
    const float* __restrict__ hx, const float* __restrict__ as,
    const float* __restrict__ ad, const float* __restrict__ bias,
    float* __restrict__ out)
{
    const int lane = threadIdx.x & 31;
    const int warp = threadIdx.x >> 5;
    const int node = blockIdx.x * 4 + (warp >> 1);
    const int h = warp & 1;
    const int D = 2 * C;
    const int base = g_rowptr[node];
    const int deg = g_rowptr[node + 1] - base;
    const float adi = ad[node * 2 + h];

    float es = as[node * 2 + h] + adi;           // self loop score
    es = es > 0.f ? es : 0.2f * es;
    float m = es;
    for (int j = lane; j < deg; j += 32) {
        int s = g_col[base + j];
        float e = as[s * 2 + h] + adi;
        e = e > 0.f ? e : 0.2f * e;
        m = fmaxf(m, e);
    }
    #pragma unroll
    for (int o = 16; o; o >>= 1) m = fmaxf(m, __shfl_xor_sync(0xffffffffu, m, o));

    constexpr int V = C / 32;  // floats per lane (2 or 4)
    float acc[V];
    #pragma unroll
    for (int v = 0; v < V; v++) acc[v] = 0.f;
    float z = 0.f;

    for (int j = 0; j < deg; j++) {
        int s = g_col[base + j];                 // warp-broadcast load
        float e = as[s * 2 + h] + adi;
        e = e > 0.f ? e : 0.2f * e;
        float p = __expf(e - m);
        z += p;
        const float* row = hx + (size_t)s * D + h * C + lane * V;
        if constexpr (V == 2) {
            float2 v2 = *(const float2*)row;
            acc[0] += p * v2.x; acc[1] += p * v2.y;
        } else {
            float4 v4 = *(const float4*)row;
            acc[0] += p * v4.x; acc[1] += p * v4.y;
            acc[2] += p * v4.z; acc[3] += p * v4.w;
        }
    }
    {   // self loop
        float p = __expf(es - m);
        z += p;
        const float* row = hx + (size_t)node * D + h * C + lane * V;
        if constexpr (V == 2) {
            float2 v2 = *(const float2*)row;
            acc[0] += p * v2.x; acc[1] += p * v2.y;
        } else {
            float4 v4 = *(const float4*)row;
            acc[0] += p * v4.x; acc[1] += p * v4.y;
            acc[2] += p * v4.z; acc[3] += p * v4.w;
        }
    }
    const float inv = 1.f / z;
    float* o = out + (size_t)node * D + h * C + lane * V;
    const float* b = bias + h * C + lane * V;
    #pragma unroll
    for (int v = 0; v < V; v++) o[v] = acc[v] * inv + b[v];
}

// ------------------------------ batch norm ----------------------------------
__global__ void bnstats_kernel(const float* __restrict__ X, int COLS) {
    const int c = threadIdx.x;          // blockDim.x == COLS
    const int r0 = blockIdx.x * 200;    // 100 blocks * 200 rows = 20000
    float s = 0.f, q = 0.f;
    for (int r = r0; r < r0 + 200; r++) {
        float v = X[(size_t)r * COLS + c];
        s += v;
        q += v * v;
    }
    g_part[blockIdx.x * 2 * COLS + c] = s;
    g_part[blockIdx.x * 2 * COLS + COLS + c] = q;
}

__global__ void bnfin_kernel(const float* __restrict__ gamma,
                             const float* __restrict__ beta, int COLS) {
    const int c = threadIdx.x;
    float s = 0.f, q = 0.f;
    for (int b = 0; b < 100; b++) {
        s += g_part[b * 2 * COLS + c];
        q += g_part[b * 2 * COLS + COLS + c];
    }
    const float mu = s * (1.f / NN);
    const float var = q * (1.f / NN) - mu * mu;
    const float sc = gamma[c] * rsqrtf(var + 1e-5f);
    g_scale[c] = sc;
    g_shift[c] = beta[c] - mu * sc;
}

__global__ void bnapply_kernel(const float* __restrict__ X,
                               float* __restrict__ Y, int mask, int total) {
    int i = blockIdx.x * blockDim.x + threadIdx.x;
    if (i >= total) return;
    int c = i & mask;   // COLS is a power of two
    float y = X[i] * g_scale[c] + g_shift[c];
    Y[i] = y > 0.f ? y : 0.f;
}

// ------------------------------- launcher -----------------------------------
extern "C" void kernel_launch(void* const* d_in, const int* in_sizes, int n_in,
                              void* d_out, int out_size) {
    const float* x        = (const float*)d_in[0];
    const void*  ei       = d_in[1];
    const float* W1       = (const float*)d_in[2];
    const float* att_src1 = (const float*)d_in[3];
    const float* att_dst1 = (const float*)d_in[4];
    const float* bias1    = (const float*)d_in[5];
    const float* gamma1   = (const float*)d_in[6];
    const float* beta1    = (const float*)d_in[7];
    const float* W2       = (const float*)d_in[8];
    const float* att_src2 = (const float*)d_in[9];
    const float* att_dst2 = (const float*)d_in[10];
    const float* bias2    = (const float*)d_in[11];
    const float* gamma2   = (const float*)d_in[12];
    const float* beta2    = (const float*)d_in[13];
    float* out = (float*)d_out;

    float *hx1, *as1, *ad1, *out1, *hx2, *as2, *ad2, *out2;
    cudaGetSymbolAddress((void**)&hx1,  g_hx1);
    cudaGetSymbolAddress((void**)&as1,  g_as1);
    cudaGetSymbolAddress((void**)&ad1,  g_ad1);
    cudaGetSymbolAddress((void**)&out1, g_out1);
    cudaGetSymbolAddress((void**)&hx2,  g_hx2);
    cudaGetSymbolAddress((void**)&as2,  g_as2);
    cudaGetSymbolAddress((void**)&ad2,  g_ad2);
    cudaGetSymbolAddress((void**)&out2, g_out2);

    // ---- CSR build ----
    zero_detect_kernel<<<(NN + 255) / 256, 256>>>((const int*)ei);
    hist_kernel<<<EE / 256, 256>>>(ei);
    scan_kernel<<<1, 1024>>>();
    scatter_kernel<<<EE / 256, 256>>>(ei);

    // ---- layer 1 ----
    gemm_kernel<<<dim3((NN + 63) / 64, 1), 256>>>(x, W1, hx1, NN, FF, D1);
    scores_kernel<<<NN / 8, 256>>>(hx1, att_src1, att_dst1, as1, ad1, 64);
    agg_kernel<64><<<NN / 4, 256>>>(hx1, as1, ad1, bias1, out1);
    bnstats_kernel<<<100, D1>>>(out1, D1);
    bnfin_kernel<<<1, D1>>>(gamma1, beta1, D1);
    bnapply_kernel<<<(NN * D1 + 255) / 256, 256>>>(out1, out1, D1 - 1, NN * D1);

    // ---- layer 2 ----
    gemm_kernel<<<dim3((NN + 63) / 64, 2), 256>>>(out1, W2, hx2, NN, D1, D2);
    scores_kernel<<<NN / 8, 256>>>(hx2, att_src2, att_dst2, as2, ad2, 128);
    agg_kernel<128><<<NN / 4, 256>>>(hx2, as2, ad2, bias2, out2);
    bnstats_kernel<<<100, D2>>>(out2, D2);
    bnfin_kernel<<<1, D2>>>(gamma2, beta2, D2);
    bnapply_kernel<<<(NN * D2 + 255) / 256, 256>>>(out2, out, D2 - 1, NN * D2);
}

// round 2
// speedup vs baseline: 1.2107x; 1.2107x over previous
#include <cuda_runtime.h>
#include <cuda_fp16.h>
#include <cuda_bf16.h>
#include <math.h>

// ---------------------------------------------------------------------------
// GATLayers: 2x (GATConv -> BatchNorm -> ReLU).
//   N=20000, E=640000 (+N self loops), F=64, H=2
// Round-2 strategy:
//   - hx stored fp16 (GEMM fp32 compute, half store) -> halve gather traffic
//   - agg: one warp per node serves BOTH heads, single pass (no max needed:
//     scores are O(1), exp() safe in fp32), self-loop analytic, zero atomics
//   - GEMM: fp32 with packed fma.rn.f32x2 (2 FMA/inst), BN+ReLU of layer 1
//     fused into gemm2's A-tile load
//   - CSR: rank recorded during histogram -> scatter has no atomics
// ---------------------------------------------------------------------------

constexpr int NN = 20000;
constexpr int EE = 640000;
constexpr int FF = 64;
constexpr int D1 = 128;   // H*C1
constexpr int D2 = 256;   // H*C2

// ------------------------------ scratch ------------------------------------
__device__ int    g_is64;
__device__ int    g_deg[NN];
__device__ int    g_rowptr[NN + 1];
__device__ int    g_rank[EE];
__device__ int    g_col[EE];
__device__ __half g_hx1[NN * D1];
__device__ float  g_as1[NN * 2];
__device__ float  g_ad1[NN * 2];
__device__ float  g_out1[NN * D1];
__device__ __half g_hx2[NN * D2];
__device__ float  g_as2[NN * 2];
__device__ float  g_ad2[NN * 2];
__device__ float  g_out2[NN * D2];
__device__ float  g_part[100 * 2 * 256];
__device__ float  g_scale[256];
__device__ float  g_shift[256];

// --------------------------- f32x2 helpers ----------------------------------
__device__ __forceinline__ unsigned long long pack2(float lo, float hi) {
    unsigned long long r;
    asm("mov.b64 %0, {%1, %2};" : "=l"(r)
        : "r"(__float_as_uint(lo)), "r"(__float_as_uint(hi)));
    return r;
}
__device__ __forceinline__ void unpk2(unsigned long long v, float& x, float& y) {
    unsigned a, b;
    asm("mov.b64 {%0, %1}, %2;" : "=r"(a), "=r"(b) : "l"(v));
    x = __uint_as_float(a); y = __uint_as_float(b);
}
__device__ __forceinline__ void ffma2(unsigned long long& d,
                                      unsigned long long a,
                                      unsigned long long b) {
    asm("fma.rn.f32x2 %0, %1, %2, %0;" : "+l"(d) : "l"(a), "l"(b));
}

// -------------------------- CSR construction -------------------------------
__global__ void zero_detect_kernel(const int* __restrict__ ei32) {
    int i = blockIdx.x * blockDim.x + threadIdx.x;
    if (i < NN) g_deg[i] = 0;
    if (i == 0) {
        int is64 = 1;
        for (int k = 0; k < 64; k++)
            if (ei32[2 * k + 1] != 0) { is64 = 0; break; }
        g_is64 = is64;
    }
}

__device__ __forceinline__ int edge_val(const void* ei, int idx, int is64) {
    if (is64) return (int)((const long long*)ei)[idx];
    return ((const int*)ei)[idx];
}

__global__ void hist_kernel(const void* __restrict__ ei) {
    int e = blockIdx.x * blockDim.x + threadIdx.x;
    if (e >= EE) return;
    int dst = edge_val(ei, EE + e, g_is64);
    g_rank[e] = atomicAdd(&g_deg[dst], 1);
}

__global__ __launch_bounds__(1024) void scan_kernel() {
    __shared__ int s[1024];
    const int t = threadIdx.x;
    const int chunk = (NN + 1023) / 1024;  // 20
    int lo = t * chunk;
    int hi = lo + chunk; if (hi > NN) hi = NN;
    if (lo > NN) lo = NN;
    int sum = 0;
    for (int i = lo; i < hi; i++) sum += g_deg[i];
    s[t] = sum;
    __syncthreads();
    for (int off = 1; off < 1024; off <<= 1) {
        int v = (t >= off) ? s[t - off] : 0;
        __syncthreads();
        s[t] += v;
        __syncthreads();
    }
    int run = s[t] - sum;
    for (int i = lo; i < hi; i++) {
        g_rowptr[i] = run;
        run += g_deg[i];
    }
    if (t == 1023) g_rowptr[NN] = s[1023];
}

__global__ void scatter_kernel(const void* __restrict__ ei) {
    int e = blockIdx.x * blockDim.x + threadIdx.x;
    if (e >= EE) return;
    int is64 = g_is64;
    int src = edge_val(ei, e, is64);
    int dst = edge_val(ei, EE + e, is64);
    g_col[g_rowptr[dst] + g_rank[e]] = src;
}

// ------------------------------- GEMM --------------------------------------
// C[M,Ncol] = A[M,K] @ B[K,Ncol], fp32 compute (packed f32x2 FMA), half out.
// BM=64, BN=128, BK=32, 256 threads, 8x4 outputs/thread.
// BN_A: apply y = relu(x*g_scale[col]+g_shift[col]) to A elements on load.
template <bool BN_A>
__global__ __launch_bounds__(256) void gemm_kernel(
    const float* __restrict__ A, const float* __restrict__ B,
    __half* __restrict__ C, int M, int K, int Ncol)
{
    __shared__ float As[64 * 32];
    __shared__ float Bs[32 * 128];
    const int tid = threadIdx.x;
    const int row0 = blockIdx.x * 64;
    const int col0 = blockIdx.y * 128;
    const int tx = tid & 31;
    const int ty = tid >> 5;
    unsigned long long acc[8][2];
    #pragma unroll
    for (int i = 0; i < 8; i++) { acc[i][0] = 0ull; acc[i][1] = 0ull; }

    for (int k0 = 0; k0 < K; k0 += 32) {
        float sc = 1.f, sh = 0.f;
        if (BN_A) { sc = g_scale[k0 + tx]; sh = g_shift[k0 + tx]; }
        #pragma unroll
        for (int i = 0; i < 8; i++) {           // 64*32/256 = 8
            int idx = tid + i * 256;
            int r = idx >> 5, c = idx & 31;     // c == tx
            int gr = row0 + r;
            float v = (gr < M) ? A[(size_t)gr * K + k0 + c] : 0.f;
            if (BN_A) { v = v * sc + sh; v = v > 0.f ? v : 0.f; }
            As[idx] = v;
        }
        #pragma unroll
        for (int i = 0; i < 16; i++) {          // 32*128/256 = 16
            int idx = tid + i * 256;
            int r = idx >> 7, c = idx & 127;
            Bs[idx] = B[(size_t)(k0 + r) * Ncol + col0 + c];
        }
        __syncthreads();
        #pragma unroll
        for (int kk = 0; kk < 32; kk++) {
            ulonglong2 bv = *(const ulonglong2*)&Bs[kk * 128 + tx * 4];
            #pragma unroll
            for (int i = 0; i < 8; i++) {
                float a = As[(ty * 8 + i) * 32 + kk];
                unsigned long long aa = pack2(a, a);
                ffma2(acc[i][0], aa, bv.x);
                ffma2(acc[i][1], aa, bv.y);
            }
        }
        __syncthreads();
    }
    #pragma unroll
    for (int i = 0; i < 8; i++) {
        int gr = row0 + ty * 8 + i;
        if (gr < M) {
            float c0, c1, c2, c3;
            unpk2(acc[i][0], c0, c1);
            unpk2(acc[i][1], c2, c3);
            __half2 h0 = __floats2half2_rn(c0, c1);
            __half2 h1 = __floats2half2_rn(c2, c3);
            uint2 st;
            st.x = *(unsigned*)&h0;
            st.y = *(unsigned*)&h1;
            *(uint2*)(C + (size_t)gr * Ncol + col0 + tx * 4) = st;
        }
    }
}

// --------------------------- attention scores ------------------------------
// One warp per node, hx in fp16.
template <int C>
__global__ __launch_bounds__(256) void scores_kernel(
    const __half* __restrict__ hx, const float* __restrict__ att_s,
    const float* __restrict__ att_d, float* __restrict__ as_out,
    float* __restrict__ ad_out)
{
    const int lane = threadIdx.x & 31;
    const int warp = threadIdx.x >> 5;
    const int node = blockIdx.x * 8 + warp;
    const __half2* row = (const __half2*)(hx + (size_t)node * 2 * C);
    float s0 = 0.f, s1 = 0.f, d0 = 0.f, d1 = 0.f;
    #pragma unroll
    for (int u = lane; u < C; u += 32) {  // C half2 units = 2C halves
        float2 f = __half22float2(row[u]);
        int cc = 2 * u;
        float a0 = att_s[cc], a1 = att_s[cc + 1];
        float b0 = att_d[cc], b1 = att_d[cc + 1];
        if (cc < C) { s0 += f.x * a0 + f.y * a1; d0 += f.x * b0 + f.y * b1; }
        else        { s1 += f.x * a0 + f.y * a1; d1 += f.x * b0 + f.y * b1; }
    }
    #pragma unroll
    for (int o = 16; o; o >>= 1) {
        s0 += __shfl_xor_sync(0xffffffffu, s0, o);
        s1 += __shfl_xor_sync(0xffffffffu, s1, o);
        d0 += __shfl_xor_sync(0xffffffffu, d0, o);
        d1 += __shfl_xor_sync(0xffffffffu, d1, o);
    }
    if (lane == 0) {
        as_out[node * 2 + 0] = s0;
        as_out[node * 2 + 1] = s1;
        ad_out[node * 2 + 0] = d0;
        ad_out[node * 2 + 1] = d1;
    }
}

// ------------------- segment softmax + weighted aggregate ------------------
// One warp per node handling BOTH heads; single pass (no max subtraction —
// scores are O(1), exp() is safe in fp32 and p/z is invariant to the shift).
template <int C>
__global__ __launch_bounds__(256) void agg_kernel(
    const __half* __restrict__ hx, const float* __restrict__ as,
    const float* __restrict__ ad, const float* __restrict__ bias,
    float* __restrict__ out)
{
    const int lane = threadIdx.x & 31;
    const int warp = threadIdx.x >> 5;
    const int node = blockIdx.x * 8 + warp;
    constexpr int D = 2 * C;
    constexpr int V = D / 32;             // halves per lane: 4 (C=64) or 8
    const int base = g_rowptr[node];
    const int deg = g_rowptr[node + 1] - base;
    const float2* as2 = (const float2*)as;
    const float2 adi = ((const float2*)ad)[node];

    float acc[V];
    #pragma unroll
    for (int v = 0; v < V; v++) acc[v] = 0.f;
    float z0, z1;

    {   // self loop
        float2 a = as2[node];
        float e0 = a.x + adi.x; e0 = e0 > 0.f ? e0 : 0.2f * e0;
        float e1 = a.y + adi.y; e1 = e1 > 0.f ? e1 : 0.2f * e1;
        float p0 = __expf(e0), p1 = __expf(e1);
        z0 = p0; z1 = p1;
        float p = (lane < 16) ? p0 : p1;
        const __half* row = hx + (size_t)node * D + lane * V;
        if constexpr (V == 4) {
            uint2 u = *(const uint2*)row;
            float2 f0 = __half22float2(*(__half2*)&u.x);
            float2 f1 = __half22float2(*(__half2*)&u.y);
            acc[0] += p * f0.x; acc[1] += p * f0.y;
            acc[2] += p * f1.x; acc[3] += p * f1.y;
        } else {
            uint4 u = *(const uint4*)row;
            float2 f0 = __half22float2(*(__half2*)&u.x);
            float2 f1 = __half22float2(*(__half2*)&u.y);
            float2 f2 = __half22float2(*(__half2*)&u.z);
            float2 f3 = __half22float2(*(__half2*)&u.w);
            acc[0] += p * f0.x; acc[1] += p * f0.y;
            acc[2] += p * f1.x; acc[3] += p * f1.y;
            acc[4] += p * f2.x; acc[5] += p * f2.y;
            acc[6] += p * f3.x; acc[7] += p * f3.y;
        }
    }

    int s_next = (deg > 0) ? g_col[base] : 0;
    for (int j = 0; j < deg; j++) {
        int s = s_next;
        if (j + 1 < deg) s_next = g_col[base + j + 1];
        float2 a = as2[s];
        float e0 = a.x + adi.x; e0 = e0 > 0.f ? e0 : 0.2f * e0;
        float e1 = a.y + adi.y; e1 = e1 > 0.f ? e1 : 0.2f * e1;
        float p0 = __expf(e0), p1 = __expf(e1);
        z0 += p0; z1 += p1;
        float p = (lane < 16) ? p0 : p1;
        const __half* row = hx + (size_t)s * D + lane * V;
        if constexpr (V == 4) {
            uint2 u = *(const uint2*)row;
            float2 f0 = __half22float2(*(__half2*)&u.x);
            float2 f1 = __half22float2(*(__half2*)&u.y);
            acc[0] += p * f0.x; acc[1] += p * f0.y;
            acc[2] += p * f1.x; acc[3] += p * f1.y;
        } else {
            uint4 u = *(const uint4*)row;
            float2 f0 = __half22float2(*(__half2*)&u.x);
            float2 f1 = __half22float2(*(__half2*)&u.y);
            float2 f2 = __half22float2(*(__half2*)&u.z);
            float2 f3 = __half22float2(*(__half2*)&u.w);
            acc[0] += p * f0.x; acc[1] += p * f0.y;
            acc[2] += p * f1.x; acc[3] += p * f1.y;
            acc[4] += p * f2.x; acc[5] += p * f2.y;
            acc[6] += p * f3.x; acc[7] += p * f3.y;
        }
    }

    const float inv = 1.f / ((lane < 16) ? z0 : z1);
    float* o = out + (size_t)node * D + lane * V;
    const float* b = bias + lane * V;
    #pragma unroll
    for (int v = 0; v < V; v++) o[v] = acc[v] * inv + b[v];
}

// ------------------------------ batch norm ----------------------------------
__global__ void bnstats_kernel(const float* __restrict__ X, int COLS) {
    const int c = threadIdx.x;          // blockDim.x == COLS
    const int r0 = blockIdx.x * 200;    // 100 blocks * 200 rows
    float s = 0.f, q = 0.f;
    for (int r = r0; r < r0 + 200; r++) {
        float v = X[(size_t)r * COLS + c];
        s += v;
        q += v * v;
    }
    g_part[blockIdx.x * 2 * COLS + c] = s;
    g_part[blockIdx.x * 2 * COLS + COLS + c] = q;
}

__global__ void bnfin_kernel(const float* __restrict__ gamma,
                             const float* __restrict__ beta, int COLS) {
    const int c = threadIdx.x;
    float s = 0.f, q = 0.f;
    for (int b = 0; b < 100; b++) {
        s += g_part[b * 2 * COLS + c];
        q += g_part[b * 2 * COLS + COLS + c];
    }
    const float mu = s * (1.f / NN);
    const float var = q * (1.f / NN) - mu * mu;
    const float sc = gamma[c] * rsqrtf(var + 1e-5f);
    g_scale[c] = sc;
    g_shift[c] = beta[c] - mu * sc;
}

__global__ void bnapply_kernel(const float* __restrict__ X,
                               float* __restrict__ Y, int mask, int total) {
    int i = blockIdx.x * blockDim.x + threadIdx.x;
    if (i >= total) return;
    int c = i & mask;
    float y = X[i] * g_scale[c] + g_shift[c];
    Y[i] = y > 0.f ? y : 0.f;
}

// ------------------------------- launcher -----------------------------------
extern "C" void kernel_launch(void* const* d_in, const int* in_sizes, int n_in,
                              void* d_out, int out_size) {
    const float* x        = (const float*)d_in[0];
    const void*  ei       = d_in[1];
    const float* W1       = (const float*)d_in[2];
    const float* att_src1 = (const float*)d_in[3];
    const float* att_dst1 = (const float*)d_in[4];
    const float* bias1    = (const float*)d_in[5];
    const float* gamma1   = (const float*)d_in[6];
    const float* beta1    = (const float*)d_in[7];
    const float* W2       = (const float*)d_in[8];
    const float* att_src2 = (const float*)d_in[9];
    const float* att_dst2 = (const float*)d_in[10];
    const float* bias2    = (const float*)d_in[11];
    const float* gamma2   = (const float*)d_in[12];
    const float* beta2    = (const float*)d_in[13];
    float* out = (float*)d_out;

    __half *hx1, *hx2;
    float *as1, *ad1, *out1, *as2, *ad2, *out2;
    cudaGetSymbolAddress((void**)&hx1,  g_hx1);
    cudaGetSymbolAddress((void**)&as1,  g_as1);
    cudaGetSymbolAddress((void**)&ad1,  g_ad1);
    cudaGetSymbolAddress((void**)&out1, g_out1);
    cudaGetSymbolAddress((void**)&hx2,  g_hx2);
    cudaGetSymbolAddress((void**)&as2,  g_as2);
    cudaGetSymbolAddress((void**)&ad2,  g_ad2);
    cudaGetSymbolAddress((void**)&out2, g_out2);

    // ---- CSR build ----
    zero_detect_kernel<<<(NN + 255) / 256, 256>>>((const int*)ei);
    hist_kernel<<<EE / 256, 256>>>(ei);
    scan_kernel<<<1, 1024>>>();
    scatter_kernel<<<EE / 256, 256>>>(ei);

    // ---- layer 1 ----
    gemm_kernel<false><<<dim3((NN + 63) / 64, 1), 256>>>(x, W1, hx1, NN, FF, D1);
    scores_kernel<64><<<NN / 8, 256>>>(hx1, att_src1, att_dst1, as1, ad1);
    agg_kernel<64><<<NN / 8, 256>>>(hx1, as1, ad1, bias1, out1);
    bnstats_kernel<<<100, D1>>>(out1, D1);
    bnfin_kernel<<<1, D1>>>(gamma1, beta1, D1);

    // ---- layer 2 (BN1+ReLU fused into gemm2's A load) ----
    gemm_kernel<true><<<dim3((NN + 63) / 64, 2), 256>>>(out1, W2, hx2, NN, D1, D2);
    scores_kernel<128><<<NN / 8, 256>>>(hx2, att_src2, att_dst2, as2, ad2);
    agg_kernel<128><<<NN / 8, 256>>>(hx2, as2, ad2, bias2, out2);
    bnstats_kernel<<<100, D2>>>(out2, D2);
    bnfin_kernel<<<1, D2>>>(gamma2, beta2, D2);
    bnapply_kernel<<<(NN * D2 + 255) / 256, 256>>>(out2, out, D2 - 1, NN * D2);
}